// round 9
// baseline (speedup 1.0000x reference)
#include <cuda_runtime.h>
#include <math.h>
#include <stdint.h>

#define TT 2048
#define DD 1024
#define HH 2048
#define EE 8

#define BM 128
#define BN 128
#define BK 32
#define NT 384          // 8 consumer warps + 4 producer warps
#define RING 5

#define A_STRIDE 36
#define B_STRIDE 136
#define A_BUF_W (BM * A_STRIDE)            // 4608 words
#define B_BUF_W (BK * B_STRIDE)            // 4352 words
#define A_BUF_B (A_BUF_W * 4)
#define B_BUF_B (B_BUF_W * 4)
#define SMEM_DYN (RING * (A_BUF_B + B_BUF_B))   // 179200 B

// -------- device scratch (no runtime allocation allowed) --------
__device__ int   g_count[EE];
__device__ int   g_offset[EE];
__device__ int   g_tok[EE * TT];
__device__ int   g_se[2 * TT];
__device__ int   g_sp[2 * TT];
__device__ float g_wt2[2 * TT];
__device__ __align__(16) float g_x[(size_t)TT * DD];
__device__ __align__(16) float g_h[(size_t)(2 * TT + BM) * HH];
__device__ __align__(16) float g_y[(size_t)(2 * TT) * DD];

// ---------------- helpers ----------------
__device__ __forceinline__ uint32_t smem_u32(const void* p) {
    uint32_t a;
    asm("{ .reg .u64 t; cvta.to.shared.u64 t, %1; cvt.u32.u64 %0, t; }" : "=r"(a) : "l"(p));
    return a;
}
__device__ __forceinline__ uint32_t f2tf(float f) {
    uint32_t r;
    asm("cvt.rna.tf32.f32 %0, %1;" : "=r"(r) : "f"(f));
    return r;
}
#define CP_ASYNC16(dst, src) \
    asm volatile("cp.async.cg.shared.global [%0], [%1], 16;" :: "r"(dst), "l"(src) : "memory")
#define CP_COMMIT()  asm volatile("cp.async.commit_group;" ::: "memory")
#define CP_WAIT(n)   asm volatile("cp.async.wait_group %0;" :: "n"(n) : "memory")

#define MBAR_INIT(addr, cnt) \
    asm volatile("mbarrier.init.shared.b64 [%0], %1;" :: "r"(addr), "r"(cnt) : "memory")
#define MBAR_ARRIVE(addr) \
    asm volatile("mbarrier.arrive.shared.b64 _, [%0];" :: "r"(addr) : "memory")
#define MBAR_WAIT(addr, ph) do { \
    asm volatile("{\n\t.reg .pred P1;\n\tWL%=:\n\t" \
        "mbarrier.try_wait.parity.acquire.cta.shared::cta.b64 P1, [%0], %1, 0x989680;\n\t" \
        "@P1 bra.uni WD%=;\n\tbra.uni WL%=;\n\tWD%=:\n\t}" \
        :: "r"(addr), "r"(ph) : "memory"); \
} while (0)

__device__ __forceinline__ void ldsm4(uint32_t* r, uint32_t addr) {
    asm volatile("ldmatrix.sync.aligned.m8n8.x4.shared.b16 {%0,%1,%2,%3}, [%4];"
        : "=r"(r[0]), "=r"(r[1]), "=r"(r[2]), "=r"(r[3]) : "r"(addr));
}
__device__ __forceinline__ void mma_tf32(float* c, const uint32_t* a, const uint32_t* b) {
    asm volatile(
        "mma.sync.aligned.m16n8k8.row.col.f32.tf32.tf32.f32 "
        "{%0,%1,%2,%3}, {%4,%5,%6,%7}, {%8,%9}, {%0,%1,%2,%3};"
        : "+f"(c[0]), "+f"(c[1]), "+f"(c[2]), "+f"(c[3])
        : "r"(a[0]), "r"(a[1]), "r"(a[2]), "r"(a[3]), "r"(b[0]), "r"(b[1]));
}
__device__ __forceinline__ float gelu_tanh(float v) {
    float x3 = v * v * v;
    float t  = tanhf(0.7978845608028654f * (v + 0.044715f * x3));
    return 0.5f * v * (1.0f + t);
}

// ----------------------------------------------------------------
__global__ void prep_kernel(const float* __restrict__ x) {
    int i = blockIdx.x * blockDim.x + threadIdx.x;
    if (i < EE) g_count[i] = 0;
    const int n4 = TT * DD / 4;
    const int stride = gridDim.x * blockDim.x;
    for (int j = i; j < n4; j += stride) {
        float4 v = reinterpret_cast<const float4*>(x)[j];
        uint4 u = { f2tf(v.x), f2tf(v.y), f2tf(v.z), f2tf(v.w) };
        reinterpret_cast<uint4*>(g_x)[j] = u;
    }
}

__global__ void gate_kernel(const float* __restrict__ x,
                            const float* __restrict__ Wg,
                            const float* __restrict__ bg,
                            float* __restrict__ out_idx, int write_idx) {
    int warp = (blockIdx.x * blockDim.x + threadIdx.x) >> 5;
    int lane = threadIdx.x & 31;
    if (warp >= TT) return;
    const float* xr = x + (size_t)warp * DD;

    float acc[EE];
#pragma unroll
    for (int e = 0; e < EE; e++) acc[e] = 0.0f;
    for (int d = lane; d < DD; d += 32) {
        float xv = xr[d];
        const float* wr = Wg + (size_t)d * EE;
#pragma unroll
        for (int e = 0; e < EE; e++) acc[e] += xv * wr[e];
    }
#pragma unroll
    for (int off = 16; off > 0; off >>= 1) {
#pragma unroll
        for (int e = 0; e < EE; e++)
            acc[e] += __shfl_xor_sync(0xFFFFFFFFu, acc[e], off);
    }
    if (lane == 0) {
        float v[EE];
#pragma unroll
        for (int e = 0; e < EE; e++) v[e] = acc[e] + bg[e];
        int e0 = 0;
#pragma unroll
        for (int e = 1; e < EE; e++) if (v[e] > v[e0]) e0 = e;
        int e1 = -1;
#pragma unroll
        for (int e = 0; e < EE; e++)
            if (e != e0 && (e1 < 0 || v[e] > v[e1])) e1 = e;

        float a1 = expf(v[e1] - v[e0]);
        float s  = 1.0f + a1;
        float w0 = 1.0f / s;
        float w1 = a1 / s;

        int p0 = atomicAdd(&g_count[e0], 1);
        g_tok[e0 * TT + p0] = warp;
        int p1 = atomicAdd(&g_count[e1], 1);
        g_tok[e1 * TT + p1] = warp;

        g_se[2 * warp] = e0;  g_sp[2 * warp] = p0;  g_wt2[2 * warp] = w0;
        g_se[2 * warp + 1] = e1;  g_sp[2 * warp + 1] = p1;  g_wt2[2 * warp + 1] = w1;

        if (write_idx) {
            out_idx[warp * 2 + 0] = (float)e0;
            out_idx[warp * 2 + 1] = (float)e1;
        }
    }
}

__global__ void prefix_kernel() {
    if (threadIdx.x == 0) {
        int s = 0;
#pragma unroll
        for (int e = 0; e < EE; e++) { g_offset[e] = s; s += g_count[e]; }
    }
}

// ---------------- warp-specialized HMMA tf32 grouped FFN GEMM ----------------
// Threads 0..255: 8 consumer warps (4Mx2N, warp tile 32x64) — pure ldsm/LDS/mma.
// Threads 256..383: 4 producer warps — A via cp.async, B via LDG->cvt->STS.
// 5-slot ring; mbarrier full (128 arrivals) / free (256 arrivals) per slot.
template <bool SECOND>
__global__ void __launch_bounds__(NT, 1)
ffn_kernel(const float* __restrict__ W, const float* __restrict__ bias) {
    const int KDIM = SECOND ? HH : DD;
    const int NDIM = SECOND ? DD : HH;
    const int NS   = KDIM / BK;

    const int e   = blockIdx.x >> 4;
    const int mt_ = blockIdx.x & 15;
    const int cnt = g_count[e];
    const int m0  = mt_ * BM;
    if (m0 >= cnt) return;
    const int n0 = blockIdx.y * BN;
    const int gbase = g_offset[e];

    __shared__ int stok[BM];
    __shared__ __align__(8) uint64_t s_mbar[2 * RING];   // [0..4]=full, [5..9]=free
    extern __shared__ uint32_t smem[];
    uint32_t* const Bsm = smem + RING * A_BUF_W;
    const uint32_t sbase  = smem_u32(smem);
    const uint32_t mbF = smem_u32(&s_mbar[0]);
    const uint32_t mbE = smem_u32(&s_mbar[RING]);

    const int tid = threadIdx.x;
    if (tid == 0) {
#pragma unroll
        for (int j = 0; j < RING; j++) {
            MBAR_INIT(mbF + j * 8, 128u);
            MBAR_INIT(mbE + j * 8, 256u);
        }
    }
    if (!SECOND && tid < BM) {
        int r = m0 + tid;
        stok[tid] = (r < cnt) ? g_tok[e * TT + r] : g_tok[e * TT];
    }
    __syncthreads();

    if (tid < 256) {
        // ================= consumer =================
        const int lane = tid & 31;
        const int wid  = tid >> 5;
        const int wm   = wid & 3;
        const int wn   = wid >> 2;
        const int lr   = lane >> 2;
        const int lc   = lane & 3;

        const uint32_t a_lane = sbase +
            (uint32_t)(((wm * 32 + (lane & 15)) * A_STRIDE + (lane >> 4) * 4) * 4);
        const int bfrag0 = lc * B_STRIDE + wn * 64 + lr;

        float c[2][8][4];
#pragma unroll
        for (int m = 0; m < 2; m++)
#pragma unroll
            for (int n = 0; n < 8; n++)
#pragma unroll
                for (int j = 0; j < 4; j++) c[m][n][j] = 0.0f;

        int slot = 0, ph = 0;
        for (int s = 0; s < NS; s++) {
            MBAR_WAIT(mbF + slot * 8, ph);
            const uint32_t aAddr = a_lane + (uint32_t)(slot * A_BUF_B);
            const uint32_t* Bp = Bsm + slot * B_BUF_W + bfrag0;
#pragma unroll
            for (int ks = 0; ks < 4; ks++) {
                uint32_t a[2][4];
#pragma unroll
                for (int m = 0; m < 2; m++)
                    ldsm4(a[m], aAddr + m * (16 * A_STRIDE * 4) + ks * 32);
                uint32_t b[8][2];
                const uint32_t* Bk = Bp + ks * 8 * B_STRIDE;
#pragma unroll
                for (int n = 0; n < 8; n++) {
                    b[n][0] = Bk[n * 8];
                    b[n][1] = Bk[n * 8 + 4 * B_STRIDE];
                }
#pragma unroll
                for (int m = 0; m < 2; m++)
#pragma unroll
                    for (int n = 0; n < 8; n++)
                        mma_tf32(c[m][n], a[m], b[n]);
            }
            MBAR_ARRIVE(mbE + slot * 8);
            if (++slot == RING) { slot = 0; ph ^= 1; }
        }

        // ---- epilogue ----
#pragma unroll
        for (int n = 0; n < 8; n++) {
            const int col = n0 + wn * 64 + n * 8 + 2 * lc;
            const float bv0 = bias[e * NDIM + col];
            const float bv1 = bias[e * NDIM + col + 1];
#pragma unroll
            for (int m = 0; m < 2; m++) {
#pragma unroll
                for (int h = 0; h < 2; h++) {
                    const int rloc = wm * 32 + m * 16 + h * 8 + lr;
                    const int rg   = m0 + rloc;
                    if (rg < cnt) {
                        float v0 = c[m][n][2 * h + 0] + bv0;
                        float v1 = c[m][n][2 * h + 1] + bv1;
                        if (!SECOND) {
                            float2 o = { __uint_as_float(f2tf(gelu_tanh(v0))),
                                         __uint_as_float(f2tf(gelu_tanh(v1))) };
                            *reinterpret_cast<float2*>(&g_h[(size_t)(gbase + rg) * HH + col]) = o;
                        } else {
                            float2 o = { v0, v1 };
                            *reinterpret_cast<float2*>(&g_y[(size_t)(gbase + rg) * DD + col]) = o;
                        }
                    }
                }
            }
        }
    } else {
        // ================= producer =================
        const int ptid = tid - 256;             // 0..127
        const char* Agbase = SECOND ? (const char*)g_h : (const char*)g_x;
        uint32_t aoff[8];
        uint32_t adst[8];
#pragma unroll
        for (int i = 0; i < 8; i++) {
            const int row = (ptid >> 3) + 16 * i;
            if (SECOND) aoff[i] = (uint32_t)((gbase + m0 + row) * HH * 4);
            else        aoff[i] = (uint32_t)(stok[row] * DD * 4);
            adst[i] = sbase + (uint32_t)((row * A_STRIDE + (ptid & 7) * 4) * 4);
        }
        const uint32_t akq = (uint32_t)((ptid & 7) * 16);

        const float* Wb = W + (size_t)e * KDIM * NDIM + n0 + (ptid & 31) * 4;
        const int bk0 = ptid >> 5;              // 0..3
        const int bw0 = (ptid & 31) * 4;

        // prologue: A(0) in flight, B(0) in regs
#pragma unroll
        for (int i = 0; i < 8; i++)
            CP_ASYNC16(adst[i], Agbase + aoff[i] + akq);
        CP_COMMIT();
        float4 pb[8];
#pragma unroll
        for (int i = 0; i < 8; i++)
            pb[i] = *reinterpret_cast<const float4*>(Wb + (size_t)(bk0 + 4 * i) * NDIM);

        int slot = 0, ph = 0;
        for (int s = 0; s < NS; s++) {
            const int nslot = (slot + 1 == RING) ? 0 : slot + 1;
            const int nph   = (slot + 1 == RING) ? (ph ^ 1) : ph;
            if (s + 1 < NS) {
                if (s + 1 >= RING) MBAR_WAIT(mbE + nslot * 8, nph ^ 1);
                const uint32_t k0b = (uint32_t)((s + 1) * BK * 4);
#pragma unroll
                for (int i = 0; i < 8; i++)
                    CP_ASYNC16(adst[i] + (uint32_t)(nslot * A_BUF_B),
                               Agbase + aoff[i] + k0b + akq);
                CP_COMMIT();
            }
            // STS B(s)
            uint32_t* Bw = Bsm + slot * B_BUF_W;
#pragma unroll
            for (int i = 0; i < 8; i++) {
                uint4 u = { f2tf(pb[i].x), f2tf(pb[i].y), f2tf(pb[i].z), f2tf(pb[i].w) };
                *reinterpret_cast<uint4*>(&Bw[(bk0 + 4 * i) * B_STRIDE + bw0]) = u;
            }
            // LDG B(s+1)
            if (s + 1 < NS) {
                const int kw = (s + 1) * BK;
#pragma unroll
                for (int i = 0; i < 8; i++)
                    pb[i] = *reinterpret_cast<const float4*>(Wb + (size_t)(kw + bk0 + 4 * i) * NDIM);
                CP_WAIT(1);        // A(s) complete; A(s+1) may fly
            } else {
                CP_WAIT(0);        // last slab: A(NS-1) complete
            }
            MBAR_ARRIVE(mbF + slot * 8);
            slot = nslot; ph = nph;
        }
    }
}

// combine: out[t] = w0*y[slot0] + w1*y[slot1]
__global__ void combine_kernel(float* __restrict__ out) {
    const int t = blockIdx.x;
    __shared__ int   s0, s1;
    __shared__ float w0, w1;
    if (threadIdx.x == 0) {
        s0 = g_offset[g_se[2 * t]]     + g_sp[2 * t];
        s1 = g_offset[g_se[2 * t + 1]] + g_sp[2 * t + 1];
        w0 = g_wt2[2 * t];
        w1 = g_wt2[2 * t + 1];
    }
    __syncthreads();
    const int d = threadIdx.x;
    float4 y0 = reinterpret_cast<const float4*>(g_y + (size_t)s0 * DD)[d];
    float4 y1 = reinterpret_cast<const float4*>(g_y + (size_t)s1 * DD)[d];
    float4 o = { w0 * y0.x + w1 * y1.x, w0 * y0.y + w1 * y1.y,
                 w0 * y0.z + w1 * y1.z, w0 * y0.w + w1 * y1.w };
    reinterpret_cast<float4*>(out + (size_t)t * DD)[d] = o;
}

// ----------------------------------------------------------------
extern "C" void kernel_launch(void* const* d_in, const int* in_sizes, int n_in,
                              void* d_out, int out_size) {
    const float* x  = (const float*)d_in[0];
    const float* Wg = (const float*)d_in[1];
    const float* bg = (const float*)d_in[2];
    const float* W1 = (const float*)d_in[3];
    const float* b1 = (const float*)d_in[4];
    const float* W2 = (const float*)d_in[5];
    const float* b2 = (const float*)d_in[6];
    float* out = (float*)d_out;

    const int write_idx = (out_size >= TT * DD + 2 * TT) ? 1 : 0;
    float* out_idx = out + (size_t)TT * DD;

    static int attr_done = 0;
    if (!attr_done) {
        cudaFuncSetAttribute(ffn_kernel<false>, cudaFuncAttributeMaxDynamicSharedMemorySize, SMEM_DYN);
        cudaFuncSetAttribute(ffn_kernel<true>,  cudaFuncAttributeMaxDynamicSharedMemorySize, SMEM_DYN);
        attr_done = 1;
    }

    prep_kernel<<<512, 256>>>(x);
    gate_kernel<<<(TT * 32 + 255) / 256, 256>>>(x, Wg, bg, out_idx, write_idx);
    prefix_kernel<<<1, 32>>>();

    ffn_kernel<false><<<dim3(EE * 16, HH / BN), NT, SMEM_DYN>>>(W1, b1);
    ffn_kernel<true ><<<dim3(EE * 16, DD / BN), NT, SMEM_DYN>>>(W2, b2);

    combine_kernel<<<TT, 256>>>(out);
}

// round 10
// speedup vs baseline: 1.0578x; 1.0578x over previous
#include <cuda_runtime.h>
#include <math.h>
#include <stdint.h>

#define TT 2048
#define DD 1024
#define HH 2048
#define EE 8

#define BM 128
#define BN 256
#define BK 32
#define NT 256

// SMEM word layout: A 3 stages of [128][36], B 2 stages of [32][264]
#define A_STRIDE 36
#define B_STRIDE 264
#define A_BUF_W (BM * A_STRIDE)            // 4608 words
#define B_BUF_W (BK * B_STRIDE)            // 8448 words
#define A_BUF_B (A_BUF_W * 4)
#define B_BUF_B (B_BUF_W * 4)
#define SMEM_DYN (3 * A_BUF_B + 2 * B_BUF_B)   // 122880 B

// -------- device scratch (no runtime allocation allowed) --------
__device__ int   g_count[EE];
__device__ int   g_offset[EE];
__device__ int   g_tok[EE * TT];
__device__ int   g_se[2 * TT];
__device__ int   g_sp[2 * TT];
__device__ float g_wt2[2 * TT];
__device__ __align__(16) float g_x[(size_t)TT * DD];
__device__ __align__(16) float g_h[(size_t)(2 * TT + BM) * HH];
__device__ __align__(16) float g_y[(size_t)(2 * TT) * DD];

// ---------------- helpers ----------------
__device__ __forceinline__ uint32_t smem_u32(const void* p) {
    uint32_t a;
    asm("{ .reg .u64 t; cvta.to.shared.u64 t, %1; cvt.u32.u64 %0, t; }" : "=r"(a) : "l"(p));
    return a;
}
__device__ __forceinline__ uint32_t f2tf(float f) {
    uint32_t r;
    asm("cvt.rna.tf32.f32 %0, %1;" : "=r"(r) : "f"(f));
    return r;
}
#define CP_ASYNC16(dst, src) \
    asm volatile("cp.async.cg.shared.global [%0], [%1], 16;" :: "r"(dst), "l"(src) : "memory")
#define CP_COMMIT()  asm volatile("cp.async.commit_group;" ::: "memory")
#define CP_WAIT(n)   asm volatile("cp.async.wait_group %0;" :: "n"(n) : "memory")

__device__ __forceinline__ void ldsm4(uint32_t* r, uint32_t addr) {
    asm volatile("ldmatrix.sync.aligned.m8n8.x4.shared.b16 {%0,%1,%2,%3}, [%4];"
        : "=r"(r[0]), "=r"(r[1]), "=r"(r[2]), "=r"(r[3]) : "r"(addr));
}
__device__ __forceinline__ void mma_tf32(float* c, const uint32_t* a, const uint32_t* b) {
    asm volatile(
        "mma.sync.aligned.m16n8k8.row.col.f32.tf32.tf32.f32 "
        "{%0,%1,%2,%3}, {%4,%5,%6,%7}, {%8,%9}, {%0,%1,%2,%3};"
        : "+f"(c[0]), "+f"(c[1]), "+f"(c[2]), "+f"(c[3])
        : "r"(a[0]), "r"(a[1]), "r"(a[2]), "r"(a[3]), "r"(b[0]), "r"(b[1]));
}
__device__ __forceinline__ float gelu_tanh(float v) {
    float x3 = v * v * v;
    float t  = tanhf(0.7978845608028654f * (v + 0.044715f * x3));
    return 0.5f * v * (1.0f + t);
}

// ----------------------------------------------------------------
__global__ void prep_kernel(const float* __restrict__ x) {
    int i = blockIdx.x * blockDim.x + threadIdx.x;
    if (i < EE) g_count[i] = 0;
    const int n4 = TT * DD / 4;
    const int stride = gridDim.x * blockDim.x;
    for (int j = i; j < n4; j += stride) {
        float4 v = reinterpret_cast<const float4*>(x)[j];
        uint4 u = { f2tf(v.x), f2tf(v.y), f2tf(v.z), f2tf(v.w) };
        reinterpret_cast<uint4*>(g_x)[j] = u;
    }
}

__global__ void gate_kernel(const float* __restrict__ x,
                            const float* __restrict__ Wg,
                            const float* __restrict__ bg,
                            float* __restrict__ out_idx, int write_idx) {
    int warp = (blockIdx.x * blockDim.x + threadIdx.x) >> 5;
    int lane = threadIdx.x & 31;
    if (warp >= TT) return;
    const float* xr = x + (size_t)warp * DD;

    float acc[EE];
#pragma unroll
    for (int e = 0; e < EE; e++) acc[e] = 0.0f;
    for (int d = lane; d < DD; d += 32) {
        float xv = xr[d];
        const float* wr = Wg + (size_t)d * EE;
#pragma unroll
        for (int e = 0; e < EE; e++) acc[e] += xv * wr[e];
    }
#pragma unroll
    for (int off = 16; off > 0; off >>= 1) {
#pragma unroll
        for (int e = 0; e < EE; e++)
            acc[e] += __shfl_xor_sync(0xFFFFFFFFu, acc[e], off);
    }
    if (lane == 0) {
        float v[EE];
#pragma unroll
        for (int e = 0; e < EE; e++) v[e] = acc[e] + bg[e];
        int e0 = 0;
#pragma unroll
        for (int e = 1; e < EE; e++) if (v[e] > v[e0]) e0 = e;
        int e1 = -1;
#pragma unroll
        for (int e = 0; e < EE; e++)
            if (e != e0 && (e1 < 0 || v[e] > v[e1])) e1 = e;

        float a1 = expf(v[e1] - v[e0]);
        float s  = 1.0f + a1;
        float w0 = 1.0f / s;
        float w1 = a1 / s;

        int p0 = atomicAdd(&g_count[e0], 1);
        g_tok[e0 * TT + p0] = warp;
        int p1 = atomicAdd(&g_count[e1], 1);
        g_tok[e1 * TT + p1] = warp;

        g_se[2 * warp] = e0;  g_sp[2 * warp] = p0;  g_wt2[2 * warp] = w0;
        g_se[2 * warp + 1] = e1;  g_sp[2 * warp + 1] = p1;  g_wt2[2 * warp + 1] = w1;

        if (write_idx) {
            out_idx[warp * 2 + 0] = (float)e0;
            out_idx[warp * 2 + 1] = (float)e1;
        }
    }
}

__global__ void prefix_kernel() {
    if (threadIdx.x == 0) {
        int s = 0;
#pragma unroll
        for (int e = 0; e < EE; e++) { g_offset[e] = s; s += g_count[e]; }
    }
}

// ---------------- HMMA tf32 grouped FFN GEMM ----------------
// CTA tile 128x256, 256 threads = 8 warps (2 along M x 4 along N), warp tile 64x64.
// A: 3-stage cp.async ring (wait_group(1)); B: 2-stage LDG->cvt->STS.
template <bool SECOND>
__global__ void __launch_bounds__(NT, 1)
ffn_kernel(const float* __restrict__ W, const float* __restrict__ bias) {
    const int KDIM = SECOND ? HH : DD;
    const int NDIM = SECOND ? DD : HH;
    const int NS   = KDIM / BK;

    const int e   = blockIdx.x >> 4;
    const int mt_ = blockIdx.x & 15;
    const int cnt = g_count[e];
    const int m0  = mt_ * BM;
    if (m0 >= cnt) return;
    const int n0 = blockIdx.y * BN;
    const int gbase = g_offset[e];

    __shared__ int stok[BM];
    extern __shared__ uint32_t smem[];
    uint32_t* const Bsm = smem + 3 * A_BUF_W;     // [2][32][264]
    const uint32_t sbaseA = smem_u32(smem);

    const int tid  = threadIdx.x;
    const int lane = tid & 31;
    const int wid  = tid >> 5;
    const int wm   = wid & 1;      // 2 warps along M (64 rows each)
    const int wn   = wid >> 1;     // 4 warps along N (64 cols each)
    const int lr   = lane >> 2;    // 0..7
    const int lc   = lane & 3;     // 0..3

    if (!SECOND) {
        if (tid < BM) {
            int r = m0 + tid;
            stok[tid] = (r < cnt) ? g_tok[e * TT + r] : g_tok[e * TT];
        }
        __syncthreads();
    }

    // ---- A producer: 4 chunks of 16B per thread per slab ----
    const char* Agbase = SECOND ? (const char*)g_h : (const char*)g_x;
    uint32_t aoff[4];
    uint32_t adst[4];
#pragma unroll
    for (int i = 0; i < 4; i++) {
        const int row = (tid >> 3) + 32 * i;
        if (SECOND) aoff[i] = (uint32_t)((gbase + m0 + row) * HH * 4);
        else        aoff[i] = (uint32_t)(stok[row] * DD * 4);
        adst[i] = sbaseA + (uint32_t)((row * A_STRIDE + (tid & 7) * 4) * 4);
    }
    const uint32_t akq = (uint32_t)((tid & 7) * 16);

    // ---- B producer: 8 float4 per thread per slab ----
    // chunk i: k = (tid>>6) + 4*i, n-quad = (tid&63)*4
    const float* Wb = W + (size_t)e * KDIM * NDIM + n0 + (tid & 63) * 4;
    const int bk0 = tid >> 6;                          // 0..3
    const int bw0 = bk0 * B_STRIDE + (tid & 63) * 4;   // word offset in B buf

    // ---- consumer setup ----
    const uint32_t a_lane = sbaseA +
        (uint32_t)(((wm * 64 + (lane & 15)) * A_STRIDE + (lane >> 4) * 4) * 4);
    const int bfrag0 = lc * B_STRIDE + wn * 64 + lr;

    float c[4][8][4];
#pragma unroll
    for (int m = 0; m < 4; m++)
#pragma unroll
        for (int n = 0; n < 8; n++)
#pragma unroll
            for (int j = 0; j < 4; j++) c[m][n][j] = 0.0f;

    // ---- prologue: commit A groups for slabs 0,1; B slab 0 via regs ----
#pragma unroll
    for (int st = 0; st < 2; st++) {
        const uint32_t k0b = (uint32_t)(st * BK * 4);
#pragma unroll
        for (int i = 0; i < 4; i++)
            CP_ASYNC16(adst[i] + (uint32_t)(st * A_BUF_B), Agbase + aoff[i] + k0b + akq);
        CP_COMMIT();
    }
    {
        float4 pb[8];
#pragma unroll
        for (int i = 0; i < 8; i++)
            pb[i] = *reinterpret_cast<const float4*>(Wb + (size_t)(bk0 + 4 * i) * NDIM);
#pragma unroll
        for (int i = 0; i < 8; i++) {
            uint4 u = { f2tf(pb[i].x), f2tf(pb[i].y), f2tf(pb[i].z), f2tf(pb[i].w) };
            *reinterpret_cast<uint4*>(&Bsm[bw0 + i * 4 * B_STRIDE]) = u;
        }
    }
    CP_WAIT(1);
    __syncthreads();

    // ---- main loop ----
    uint32_t caOff = 0;
    uint32_t paOff = 2 * A_BUF_B;
    for (int s = 0; s < NS; s++) {
        if (s + 2 < NS) {
            const uint32_t k0b = (uint32_t)((s + 2) * BK * 4);
#pragma unroll
            for (int i = 0; i < 4; i++)
                CP_ASYNC16(adst[i] + paOff, Agbase + aoff[i] + k0b + akq);
        }
        CP_COMMIT();

        float4 pb[8];
        if (s + 1 < NS) {
            const int kw = (s + 1) * BK;
#pragma unroll
            for (int i = 0; i < 8; i++)
                pb[i] = *reinterpret_cast<const float4*>(Wb + (size_t)(kw + bk0 + 4 * i) * NDIM);
        }

        // compute slab s
        const uint32_t aAddr = a_lane + caOff;
        const uint32_t* Bp = Bsm + (s & 1) * B_BUF_W + bfrag0;
#pragma unroll
        for (int ks = 0; ks < 4; ks++) {
            uint32_t a[4][4];
#pragma unroll
            for (int m = 0; m < 4; m++)
                ldsm4(a[m], aAddr + m * (16 * A_STRIDE * 4) + ks * 32);
            uint32_t b[8][2];
            const uint32_t* Bk = Bp + ks * 8 * B_STRIDE;
#pragma unroll
            for (int n = 0; n < 8; n++) {
                b[n][0] = Bk[n * 8];
                b[n][1] = Bk[n * 8 + 4 * B_STRIDE];
            }
#pragma unroll
            for (int m = 0; m < 4; m++)
#pragma unroll
                for (int n = 0; n < 8; n++)
                    mma_tf32(c[m][n], a[m], b[n]);
        }

        if (s + 1 < NS) {
            uint32_t* Bw = Bsm + ((s + 1) & 1) * B_BUF_W;
#pragma unroll
            for (int i = 0; i < 8; i++) {
                uint4 u = { f2tf(pb[i].x), f2tf(pb[i].y), f2tf(pb[i].z), f2tf(pb[i].w) };
                *reinterpret_cast<uint4*>(&Bw[bw0 + i * 4 * B_STRIDE]) = u;
            }
            CP_WAIT(1);
            __syncthreads();
        }

        caOff = (caOff == 2 * A_BUF_B) ? 0 : caOff + A_BUF_B;
        paOff = (paOff == 2 * A_BUF_B) ? 0 : paOff + A_BUF_B;
    }

    // ---- epilogue ----
#pragma unroll
    for (int n = 0; n < 8; n++) {
        const int col = n0 + wn * 64 + n * 8 + 2 * lc;
        const float bv0 = bias[e * NDIM + col];
        const float bv1 = bias[e * NDIM + col + 1];
#pragma unroll
        for (int m = 0; m < 4; m++) {
#pragma unroll
            for (int h = 0; h < 2; h++) {
                const int rloc = wm * 64 + m * 16 + h * 8 + lr;
                const int rg   = m0 + rloc;
                if (rg < cnt) {
                    float v0 = c[m][n][2 * h + 0] + bv0;
                    float v1 = c[m][n][2 * h + 1] + bv1;
                    if (!SECOND) {
                        float2 o = { __uint_as_float(f2tf(gelu_tanh(v0))),
                                     __uint_as_float(f2tf(gelu_tanh(v1))) };
                        *reinterpret_cast<float2*>(&g_h[(size_t)(gbase + rg) * HH + col]) = o;
                    } else {
                        float2 o = { v0, v1 };
                        *reinterpret_cast<float2*>(&g_y[(size_t)(gbase + rg) * DD + col]) = o;
                    }
                }
            }
        }
    }
}

// combine: out[t] = w0*y[slot0] + w1*y[slot1]
__global__ void combine_kernel(float* __restrict__ out) {
    const int t = blockIdx.x;
    __shared__ int   s0, s1;
    __shared__ float w0, w1;
    if (threadIdx.x == 0) {
        s0 = g_offset[g_se[2 * t]]     + g_sp[2 * t];
        s1 = g_offset[g_se[2 * t + 1]] + g_sp[2 * t + 1];
        w0 = g_wt2[2 * t];
        w1 = g_wt2[2 * t + 1];
    }
    __syncthreads();
    const int d = threadIdx.x;
    float4 y0 = reinterpret_cast<const float4*>(g_y + (size_t)s0 * DD)[d];
    float4 y1 = reinterpret_cast<const float4*>(g_y + (size_t)s1 * DD)[d];
    float4 o = { w0 * y0.x + w1 * y1.x, w0 * y0.y + w1 * y1.y,
                 w0 * y0.z + w1 * y1.z, w0 * y0.w + w1 * y1.w };
    reinterpret_cast<float4*>(out + (size_t)t * DD)[d] = o;
}

// ----------------------------------------------------------------
extern "C" void kernel_launch(void* const* d_in, const int* in_sizes, int n_in,
                              void* d_out, int out_size) {
    const float* x  = (const float*)d_in[0];
    const float* Wg = (const float*)d_in[1];
    const float* bg = (const float*)d_in[2];
    const float* W1 = (const float*)d_in[3];
    const float* b1 = (const float*)d_in[4];
    const float* W2 = (const float*)d_in[5];
    const float* b2 = (const float*)d_in[6];
    float* out = (float*)d_out;

    const int write_idx = (out_size >= TT * DD + 2 * TT) ? 1 : 0;
    float* out_idx = out + (size_t)TT * DD;

    static int attr_done = 0;
    if (!attr_done) {
        cudaFuncSetAttribute(ffn_kernel<false>, cudaFuncAttributeMaxDynamicSharedMemorySize, SMEM_DYN);
        cudaFuncSetAttribute(ffn_kernel<true>,  cudaFuncAttributeMaxDynamicSharedMemorySize, SMEM_DYN);
        attr_done = 1;
    }

    prep_kernel<<<512, 256>>>(x);
    gate_kernel<<<(TT * 32 + 255) / 256, 256>>>(x, Wg, bg, out_idx, write_idx);
    prefix_kernel<<<1, 32>>>();

    ffn_kernel<false><<<dim3(EE * 16, HH / BN), NT, SMEM_DYN>>>(W1, b1);
    ffn_kernel<true ><<<dim3(EE * 16, DD / BN), NT, SMEM_DYN>>>(W2, b2);

    combine_kernel<<<TT, 256>>>(out);
}

// round 11
// speedup vs baseline: 1.4155x; 1.3382x over previous
#include <cuda_runtime.h>
#include <cuda_fp16.h>
#include <math.h>
#include <stdint.h>

#define TT 2048
#define DD 1024
#define HH 2048
#define EE 8

#define BM 128
#define BN 256
#define BK 32
#define NT 256

// SMEM: A 3 stages of [128 rows x 80B] fp16, B 2 stages of [32 rows x 528B] fp16
#define A_PITCH_B 80
#define B_PITCH_B 528
#define A_BUF_B (BM * A_PITCH_B)           // 10240
#define B_BUF_B (BK * B_PITCH_B)           // 16896
#define SMEM_DYN (3 * A_BUF_B + 2 * B_BUF_B)   // 64512 B

// -------- device scratch (no runtime allocation allowed) --------
__device__ int   g_count[EE];
__device__ int   g_offset[EE];
__device__ int   g_tok[EE * TT];
__device__ int   g_se[2 * TT];
__device__ int   g_sp[2 * TT];
__device__ float g_wt2[2 * TT];
__device__ __align__(16) __half g_x[(size_t)TT * DD];               // fp16 x
__device__ __align__(16) __half g_h[(size_t)(2 * TT + BM) * HH];    // fp16 gelu out
__device__ __align__(16) float  g_y[(size_t)(2 * TT) * DD];         // per-slot ffn2 out

// ---------------- helpers ----------------
__device__ __forceinline__ uint32_t smem_u32(const void* p) {
    uint32_t a;
    asm("{ .reg .u64 t; cvta.to.shared.u64 t, %1; cvt.u32.u64 %0, t; }" : "=r"(a) : "l"(p));
    return a;
}
__device__ __forceinline__ uint32_t h2u(__half2 h) {
    return *reinterpret_cast<uint32_t*>(&h);
}
#define CP_ASYNC16(dst, src) \
    asm volatile("cp.async.cg.shared.global [%0], [%1], 16;" :: "r"(dst), "l"(src) : "memory")
#define CP_COMMIT()  asm volatile("cp.async.commit_group;" ::: "memory")
#define CP_WAIT(n)   asm volatile("cp.async.wait_group %0;" :: "n"(n) : "memory")

__device__ __forceinline__ void ldsm4(uint32_t* r, uint32_t addr) {
    asm volatile("ldmatrix.sync.aligned.m8n8.x4.shared.b16 {%0,%1,%2,%3}, [%4];"
        : "=r"(r[0]), "=r"(r[1]), "=r"(r[2]), "=r"(r[3]) : "r"(addr));
}
__device__ __forceinline__ void ldsm4t(uint32_t* r, uint32_t addr) {
    asm volatile("ldmatrix.sync.aligned.m8n8.x4.trans.shared.b16 {%0,%1,%2,%3}, [%4];"
        : "=r"(r[0]), "=r"(r[1]), "=r"(r[2]), "=r"(r[3]) : "r"(addr));
}
__device__ __forceinline__ void mma_f16(float* c, const uint32_t* a, const uint32_t* b) {
    asm volatile(
        "mma.sync.aligned.m16n8k16.row.col.f32.f16.f16.f32 "
        "{%0,%1,%2,%3}, {%4,%5,%6,%7}, {%8,%9}, {%0,%1,%2,%3};"
        : "+f"(c[0]), "+f"(c[1]), "+f"(c[2]), "+f"(c[3])
        : "r"(a[0]), "r"(a[1]), "r"(a[2]), "r"(a[3]), "r"(b[0]), "r"(b[1]));
}
__device__ __forceinline__ float gelu_tanh(float v) {
    float x3 = v * v * v;
    float t  = tanhf(0.7978845608028654f * (v + 0.044715f * x3));
    return 0.5f * v * (1.0f + t);
}

// ----------------------------------------------------------------
// prep: fp16-round x into g_x, zero counters
__global__ void prep_kernel(const float* __restrict__ x) {
    int i = blockIdx.x * blockDim.x + threadIdx.x;
    if (i < EE) g_count[i] = 0;
    const int n4 = TT * DD / 4;
    const int stride = gridDim.x * blockDim.x;
    for (int j = i; j < n4; j += stride) {
        float4 v = reinterpret_cast<const float4*>(x)[j];
        uint2 u = { h2u(__floats2half2_rn(v.x, v.y)), h2u(__floats2half2_rn(v.z, v.w)) };
        reinterpret_cast<uint2*>(g_x)[j] = u;
    }
}

__global__ void gate_kernel(const float* __restrict__ x,
                            const float* __restrict__ Wg,
                            const float* __restrict__ bg,
                            float* __restrict__ out_idx, int write_idx) {
    int warp = (blockIdx.x * blockDim.x + threadIdx.x) >> 5;
    int lane = threadIdx.x & 31;
    if (warp >= TT) return;
    const float* xr = x + (size_t)warp * DD;

    float acc[EE];
#pragma unroll
    for (int e = 0; e < EE; e++) acc[e] = 0.0f;
    for (int d = lane; d < DD; d += 32) {
        float xv = xr[d];
        const float* wr = Wg + (size_t)d * EE;
#pragma unroll
        for (int e = 0; e < EE; e++) acc[e] += xv * wr[e];
    }
#pragma unroll
    for (int off = 16; off > 0; off >>= 1) {
#pragma unroll
        for (int e = 0; e < EE; e++)
            acc[e] += __shfl_xor_sync(0xFFFFFFFFu, acc[e], off);
    }
    if (lane == 0) {
        float v[EE];
#pragma unroll
        for (int e = 0; e < EE; e++) v[e] = acc[e] + bg[e];
        int e0 = 0;
#pragma unroll
        for (int e = 1; e < EE; e++) if (v[e] > v[e0]) e0 = e;
        int e1 = -1;
#pragma unroll
        for (int e = 0; e < EE; e++)
            if (e != e0 && (e1 < 0 || v[e] > v[e1])) e1 = e;

        float a1 = expf(v[e1] - v[e0]);
        float s  = 1.0f + a1;
        float w0 = 1.0f / s;
        float w1 = a1 / s;

        int p0 = atomicAdd(&g_count[e0], 1);
        g_tok[e0 * TT + p0] = warp;
        int p1 = atomicAdd(&g_count[e1], 1);
        g_tok[e1 * TT + p1] = warp;

        g_se[2 * warp] = e0;  g_sp[2 * warp] = p0;  g_wt2[2 * warp] = w0;
        g_se[2 * warp + 1] = e1;  g_sp[2 * warp + 1] = p1;  g_wt2[2 * warp + 1] = w1;

        if (write_idx) {
            out_idx[warp * 2 + 0] = (float)e0;
            out_idx[warp * 2 + 1] = (float)e1;
        }
    }
}

__global__ void prefix_kernel() {
    if (threadIdx.x == 0) {
        int s = 0;
#pragma unroll
        for (int e = 0; e < EE; e++) { g_offset[e] = s; s += g_count[e]; }
    }
}

// ---------------- fp16 HMMA grouped FFN GEMM ----------------
// CTA 128x256, 8 warps (2M x 4N), warp tile 64x64, m16n8k16.
// A: fp16 src (g_x / g_h), 3-stage cp.async ring, wait_group(1).
// B: fp32 W -> cvt fp16 -> STS, 2-stage; consumed via ldmatrix.trans.
template <bool SECOND>
__global__ void __launch_bounds__(NT, 1)
ffn_kernel(const float* __restrict__ W, const float* __restrict__ bias) {
    const int KDIM = SECOND ? HH : DD;
    const int NDIM = SECOND ? DD : HH;
    const int NS   = KDIM / BK;

    const int e   = blockIdx.x >> 4;
    const int mt_ = blockIdx.x & 15;
    const int cnt = g_count[e];
    const int m0  = mt_ * BM;
    if (m0 >= cnt) return;
    const int n0 = blockIdx.y * BN;
    const int gbase = g_offset[e];

    __shared__ int stok[BM];
    extern __shared__ uint32_t smem[];
    const uint32_t sbaseA = smem_u32(smem);
    const uint32_t sbaseB = sbaseA + 3 * A_BUF_B;

    const int tid  = threadIdx.x;
    const int lane = tid & 31;
    const int wid  = tid >> 5;
    const int wm   = wid & 1;      // 2 warps along M
    const int wn   = wid >> 1;     // 4 warps along N
    const int lr   = lane >> 2;
    const int lc   = lane & 3;

    if (!SECOND) {
        if (tid < BM) {
            int r = m0 + tid;
            stok[tid] = (r < cnt) ? g_tok[e * TT + r] : g_tok[e * TT];
        }
        __syncthreads();
    }

    // ---- A producer: 2 chunks of 16B per thread per slab ----
    // thread t: row = t>>1, chunk pair q0 = (t&1)*2
    const char* Agbase = SECOND ? (const char*)g_h : (const char*)g_x;
    const int arow = tid >> 1;
    uint32_t aoff;                           // byte offset of row in source
    if (SECOND) aoff = (uint32_t)((gbase + m0 + arow) * HH * 2);
    else        aoff = (uint32_t)(stok[arow] * DD * 2);
    const uint32_t aq   = (uint32_t)((tid & 1) * 32);
    const uint32_t adst = sbaseA + (uint32_t)(arow * A_PITCH_B) + aq;

    // ---- B producer: 4 rows x 8 fp32 per thread per slab ----
    // thread t: n-oct = (t&31)*8, rows k = (t>>5) + 8i
    const float* Wb = W + (size_t)e * KDIM * NDIM + n0 + (tid & 31) * 8;
    const int bk0 = tid >> 5;                // 0..7
    const uint32_t bsts0 = sbaseB + (uint32_t)(bk0 * B_PITCH_B + (tid & 31) * 16);

    // ---- consumer setup ----
    // A ldsm (non-trans): lanes 0-15 rows m0-15 (k-half 0), 16-31 same rows (k-half 1)
    const uint32_t a_lane = sbaseA +
        (uint32_t)((wm * 64 + (lane & 15)) * A_PITCH_B + (lane >> 4) * 16);
    // B ldsm.trans: k = (lane&7) + ((lane>>3)&1)*8 ; n += 8 for lanes>=16
    const uint32_t b_lane = sbaseB +
        (uint32_t)(((lane & 7) + ((lane >> 3) & 1) * 8) * B_PITCH_B
                   + (wn * 64 + ((lane >> 4) & 1) * 8) * 2);

    float c[4][8][4];
#pragma unroll
    for (int m = 0; m < 4; m++)
#pragma unroll
        for (int n = 0; n < 8; n++)
#pragma unroll
            for (int j = 0; j < 4; j++) c[m][n][j] = 0.0f;

    // ---- prologue: commit A slabs 0,1; B slab 0 via regs ----
#pragma unroll
    for (int st = 0; st < 2; st++) {
        const uint32_t k0b = (uint32_t)(st * 64);    // BK halfs = 64 bytes
        CP_ASYNC16(adst + (uint32_t)(st * A_BUF_B),      Agbase + aoff + k0b + aq);
        CP_ASYNC16(adst + (uint32_t)(st * A_BUF_B) + 16, Agbase + aoff + k0b + aq + 16);
        CP_COMMIT();
    }
    {
        float4 pb[8];
#pragma unroll
        for (int i = 0; i < 4; i++) {
            const float* wr = Wb + (size_t)(bk0 + 8 * i) * NDIM;
            pb[2 * i]     = *reinterpret_cast<const float4*>(wr);
            pb[2 * i + 1] = *reinterpret_cast<const float4*>(wr + 4);
        }
#pragma unroll
        for (int i = 0; i < 4; i++) {
            uint4 u = { h2u(__floats2half2_rn(pb[2*i].x,   pb[2*i].y)),
                        h2u(__floats2half2_rn(pb[2*i].z,   pb[2*i].w)),
                        h2u(__floats2half2_rn(pb[2*i+1].x, pb[2*i+1].y)),
                        h2u(__floats2half2_rn(pb[2*i+1].z, pb[2*i+1].w)) };
            *reinterpret_cast<uint4*>(
                reinterpret_cast<char*>(smem) + (bsts0 - sbaseA) + 3 * A_BUF_B * 0
                + i * 8 * B_PITCH_B) = u;   // placeholder replaced below
        }
    }
    // NOTE: the generic-pointer store above must alias the same SMEM as bsts0;
    // rewrite with explicit st.shared to avoid any aliasing ambiguity:
    // (done in the loop below for all slabs including slab 0 — see bsts_store)

    CP_WAIT(1);
    __syncthreads();

    // ---- main loop ----
    uint32_t caOff = 0;
    uint32_t paOff = 2 * A_BUF_B;
    for (int s = 0; s < NS; s++) {
        if (s + 2 < NS) {
            const uint32_t k0b = (uint32_t)((s + 2) * 64);
            CP_ASYNC16(adst + paOff,      Agbase + aoff + k0b + aq);
            CP_ASYNC16(adst + paOff + 16, Agbase + aoff + k0b + aq + 16);
        }
        CP_COMMIT();

        float4 pb[8];
        if (s + 1 < NS) {
            const int kw = (s + 1) * BK;
#pragma unroll
            for (int i = 0; i < 4; i++) {
                const float* wr = Wb + (size_t)(kw + bk0 + 8 * i) * NDIM;
                pb[2 * i]     = *reinterpret_cast<const float4*>(wr);
                pb[2 * i + 1] = *reinterpret_cast<const float4*>(wr + 4);
            }
        }

        // compute slab s
        const uint32_t aAddr = a_lane + caOff;
        const uint32_t bAddr = b_lane + (uint32_t)((s & 1) * B_BUF_B);
#pragma unroll
        for (int ks = 0; ks < 2; ks++) {
            uint32_t a[4][4];
#pragma unroll
            for (int m = 0; m < 4; m++)
                ldsm4(a[m], aAddr + m * (16 * A_PITCH_B) + ks * 32);
            uint32_t b[8][2];
#pragma unroll
            for (int j = 0; j < 4; j++) {
                uint32_t r[4];
                ldsm4t(r, bAddr + ks * (16 * B_PITCH_B) + j * 32);
                b[2 * j][0] = r[0];  b[2 * j][1] = r[1];
                b[2 * j + 1][0] = r[2];  b[2 * j + 1][1] = r[3];
            }
#pragma unroll
            for (int m = 0; m < 4; m++)
#pragma unroll
                for (int n = 0; n < 8; n++)
                    mma_f16(c[m][n], a[m], b[n]);
        }

        if (s + 1 < NS) {
            const uint32_t bsts = bsts0 + (uint32_t)(((s + 1) & 1) * B_BUF_B);
#pragma unroll
            for (int i = 0; i < 4; i++) {
                uint32_t u0 = h2u(__floats2half2_rn(pb[2*i].x,   pb[2*i].y));
                uint32_t u1 = h2u(__floats2half2_rn(pb[2*i].z,   pb[2*i].w));
                uint32_t u2 = h2u(__floats2half2_rn(pb[2*i+1].x, pb[2*i+1].y));
                uint32_t u3 = h2u(__floats2half2_rn(pb[2*i+1].z, pb[2*i+1].w));
                asm volatile("st.shared.v4.b32 [%0], {%1, %2, %3, %4};"
                    :: "r"(bsts + (uint32_t)(i * 8 * B_PITCH_B)),
                       "r"(u0), "r"(u1), "r"(u2), "r"(u3));
            }
            CP_WAIT(1);
            __syncthreads();
        }

        caOff = (caOff == 2 * A_BUF_B) ? 0 : caOff + A_BUF_B;
        paOff = (paOff == 2 * A_BUF_B) ? 0 : paOff + A_BUF_B;
    }

    // ---- epilogue ----
#pragma unroll
    for (int n = 0; n < 8; n++) {
        const int col = n0 + wn * 64 + n * 8 + 2 * lc;
        const float bv0 = bias[e * NDIM + col];
        const float bv1 = bias[e * NDIM + col + 1];
#pragma unroll
        for (int m = 0; m < 4; m++) {
#pragma unroll
            for (int h = 0; h < 2; h++) {
                const int rloc = wm * 64 + m * 16 + h * 8 + lr;
                const int rg   = m0 + rloc;
                if (rg < cnt) {
                    float v0 = c[m][n][2 * h + 0] + bv0;
                    float v1 = c[m][n][2 * h + 1] + bv1;
                    if (!SECOND) {
                        __half2 o = __floats2half2_rn(gelu_tanh(v0), gelu_tanh(v1));
                        *reinterpret_cast<__half2*>(&g_h[(size_t)(gbase + rg) * HH + col]) = o;
                    } else {
                        float2 o = { v0, v1 };
                        *reinterpret_cast<float2*>(&g_y[(size_t)(gbase + rg) * DD + col]) = o;
                    }
                }
            }
        }
    }
}

// combine: out[t] = w0*y[slot0] + w1*y[slot1]
__global__ void combine_kernel(float* __restrict__ out) {
    const int t = blockIdx.x;
    __shared__ int   s0, s1;
    __shared__ float w0, w1;
    if (threadIdx.x == 0) {
        s0 = g_offset[g_se[2 * t]]     + g_sp[2 * t];
        s1 = g_offset[g_se[2 * t + 1]] + g_sp[2 * t + 1];
        w0 = g_wt2[2 * t];
        w1 = g_wt2[2 * t + 1];
    }
    __syncthreads();
    const int d = threadIdx.x;
    float4 y0 = reinterpret_cast<const float4*>(g_y + (size_t)s0 * DD)[d];
    float4 y1 = reinterpret_cast<const float4*>(g_y + (size_t)s1 * DD)[d];
    float4 o = { w0 * y0.x + w1 * y1.x, w0 * y0.y + w1 * y1.y,
                 w0 * y0.z + w1 * y1.z, w0 * y0.w + w1 * y1.w };
    reinterpret_cast<float4*>(out + (size_t)t * DD)[d] = o;
}

// ----------------------------------------------------------------
extern "C" void kernel_launch(void* const* d_in, const int* in_sizes, int n_in,
                              void* d_out, int out_size) {
    const float* x  = (const float*)d_in[0];
    const float* Wg = (const float*)d_in[1];
    const float* bg = (const float*)d_in[2];
    const float* W1 = (const float*)d_in[3];
    const float* b1 = (const float*)d_in[4];
    const float* W2 = (const float*)d_in[5];
    const float* b2 = (const float*)d_in[6];
    float* out = (float*)d_out;

    const int write_idx = (out_size >= TT * DD + 2 * TT) ? 1 : 0;
    float* out_idx = out + (size_t)TT * DD;

    static int attr_done = 0;
    if (!attr_done) {
        cudaFuncSetAttribute(ffn_kernel<false>, cudaFuncAttributeMaxDynamicSharedMemorySize, SMEM_DYN);
        cudaFuncSetAttribute(ffn_kernel<true>,  cudaFuncAttributeMaxDynamicSharedMemorySize, SMEM_DYN);
        attr_done = 1;
    }

    prep_kernel<<<512, 256>>>(x);
    gate_kernel<<<(TT * 32 + 255) / 256, 256>>>(x, Wg, bg, out_idx, write_idx);
    prefix_kernel<<<1, 32>>>();

    ffn_kernel<false><<<dim3(EE * 16, HH / BN), NT, SMEM_DYN>>>(W1, b1);
    ffn_kernel<true ><<<dim3(EE * 16, DD / BN), NT, SMEM_DYN>>>(W2, b2);

    combine_kernel<<<TT, 256>>>(out);
}